// round 4
// baseline (speedup 1.0000x reference)
#include <cuda_runtime.h>

#define NUM_HEADS 4
#define D 100               // WORD_DIM
#define D4 25               // D/4
#define NW 39               // words per group
#define ALPHA 0.3f
#define NT 160
#define TILE_FLOATS 4000    // 40*100 floats per (b,t,e) group
#define TILE_VEC4 1000

__device__ __forceinline__ float leaky(float p) {
    // FMNMX + FMNMX + FFMA, no predicate chain
    return fmaf(ALPHA, fminf(p, 0.f), fmaxf(p, 0.f));
}

__global__ __launch_bounds__(NT, 8)   // cap regs at 51 -> 8 blocks/SM (40 warps)
void tse_kernel(const float* __restrict__ x,
                const float* __restrict__ w_att,
                const float* __restrict__ b_att,
                float* __restrict__ out,
                int n_groups)
{
    __shared__ float  s_words[NW * D];        // 15.6 KB, rows float4-aligned (100%4==0)
    __shared__ float4 s_type4[D4];
    __shared__ float4 s_wa4[NUM_HEADS * D4];  // flat == w_att layout
    __shared__ float4 s_ba4[NUM_HEADS * D4];
    __shared__ float4 s_e4[NW];               // exp(scores), 4 heads per word
    __shared__ float  s_sum[NUM_HEADS];
    __shared__ int    s_nz;

    const int t = threadIdx.x;
    const int g = blockIdx.x;
    if (g >= n_groups) return;

    // ---- phase 0: init + params (contiguous float copy; source L2-resident) ----
    if (t == 0) s_nz = 0;
    if (t < NUM_HEADS) s_sum[t] = 0.f;
    {
        float* wa = (float*)s_wa4;
        float* ba = (float*)s_ba4;
        for (int i = t; i < NUM_HEADS * D; i += NT) {
            wa[i] = w_att[i];
            ba[i] = b_att[i];
        }
    }
    __syncthreads();   // orders s_nz/s_sum init before their first use

    // ---- phase 1: stage 40x100 tile (LDG.128 + STS.128, conflict-free) ----
    const float4* __restrict__ gx4 =
        reinterpret_cast<const float4*>(x + (size_t)g * TILE_FLOATS);
    bool flag = false;
    for (int i4 = t; i4 < TILE_VEC4; i4 += NT) {
        float4 v = gx4[i4];
        flag |= (v.x != 0.f) | (v.y != 0.f) | (v.z != 0.f) | (v.w != 0.f);
        int w = i4 / D4;           // word row (0 = type_emb)
        int j = i4 - w * D4;       // float4 column
        if (w == 0) s_type4[j] = v;
        else        *reinterpret_cast<float4*>(&s_words[(w - 1) * D + 4 * j]) = v;
    }
    unsigned any = __ballot_sync(0xffffffffu, flag);
    if ((t & 31) == 0 && any) atomicOr(&s_nz, 1);
    __syncthreads();

    // ---- phase 2: one thread per (head-pair, word): 78 threads, 2 accums ----
    if (t < 2 * NW) {
        const int hp = t / NW;               // head pair 0/1
        const int n  = t - hp * NW;
        const int h0 = hp * 2, h1 = h0 + 1;
        const float4* __restrict__ wr4 = reinterpret_cast<const float4*>(&s_words[n * D]);
        const float4* __restrict__ wa0 = &s_wa4[h0 * D4];
        const float4* __restrict__ ba0 = &s_ba4[h0 * D4];
        const float4* __restrict__ wa1 = &s_wa4[h1 * D4];
        const float4* __restrict__ ba1 = &s_ba4[h1 * D4];
        float a0 = 0.f, a1 = 0.f;
        #pragma unroll 2
        for (int j = 0; j < D4; ++j) {
            float4 w  = wr4[j];
            float4 ty = s_type4[j];
            float4 A = wa0[j], B = ba0[j];
            a0 = fmaf(ty.x, leaky(fmaf(w.x, A.x, B.x)), a0);
            a0 = fmaf(ty.y, leaky(fmaf(w.y, A.y, B.y)), a0);
            a0 = fmaf(ty.z, leaky(fmaf(w.z, A.z, B.z)), a0);
            a0 = fmaf(ty.w, leaky(fmaf(w.w, A.w, B.w)), a0);
            A = wa1[j]; B = ba1[j];
            a1 = fmaf(ty.x, leaky(fmaf(w.x, A.x, B.x)), a1);
            a1 = fmaf(ty.y, leaky(fmaf(w.y, A.y, B.y)), a1);
            a1 = fmaf(ty.z, leaky(fmaf(w.z, A.z, B.z)), a1);
            a1 = fmaf(ty.w, leaky(fmaf(w.w, A.w, B.w)), a1);
        }
        float e0 = __expf(a0), e1 = __expf(a1);
        float* ef = (float*)s_e4;
        ef[n * 4 + h0] = e0;
        ef[n * 4 + h1] = e1;
        atomicAdd(&s_sum[h0], e0);
        atomicAdd(&s_sum[h1], e1);
    }
    __syncthreads();

    // ---- phase 3/4: one thread per column d, all 4 heads ----
    if (t < D) {
        float a0 = 0.f, a1 = 0.f, a2 = 0.f, a3 = 0.f;
        #pragma unroll 13
        for (int n = 0; n < NW; ++n) {
            float  w = s_words[n * D + t];   // 1 conflict-free wf
            float4 e = s_e4[n];              // LDS.128 broadcast
            a0 = fmaf(e.x, w, a0);
            a1 = fmaf(e.y, w, a1);
            a2 = fmaf(e.z, w, a2);
            a3 = fmaf(e.w, w, a3);
        }
        const float i0 = __fdividef(1.f, s_sum[0]);
        const float i1 = __fdividef(1.f, s_sum[1]);
        const float i2 = __fdividef(1.f, s_sum[2]);
        const float i3 = __fdividef(1.f, s_sum[3]);
        float* __restrict__ go = out + (size_t)g * (NUM_HEADS * D);
        if (s_nz) {
            go[t]         = a0 * i0;
            go[D + t]     = a1 * i1;
            go[2 * D + t] = a2 * i2;
            go[3 * D + t] = a3 * i3;
        } else {
            go[t] = 0.f; go[D + t] = 0.f; go[2 * D + t] = 0.f; go[3 * D + t] = 0.f;
        }
    }
}

extern "C" void kernel_launch(void* const* d_in, const int* in_sizes, int n_in,
                              void* d_out, int out_size)
{
    const float* x     = (const float*)d_in[0];
    const float* w_att = (const float*)d_in[1];
    const float* b_att = (const float*)d_in[2];
    float* out = (float*)d_out;

    int n_groups = in_sizes[0] / TILE_FLOATS;   // B*T*E = 4800
    tse_kernel<<<n_groups, NT>>>(x, w_att, b_att, out, n_groups);
}

// round 5
// speedup vs baseline: 1.2949x; 1.2949x over previous
#include <cuda_runtime.h>

#define NUM_HEADS 4
#define D 100               // WORD_DIM
#define D4 25               // D/4
#define NW 39               // words per group
#define ALPHA 0.3f
#define NT 160
#define TILE_FLOATS 4000    // 40*100 floats per (b,t,e) group
#define TILE_VEC4 1000

__device__ __forceinline__ float leaky(float p) {
    return fmaf(ALPHA, fminf(p, 0.f), fmaxf(p, 0.f));
}

__global__ __launch_bounds__(NT, 10)
void tse_kernel(const float* __restrict__ x,
                const float* __restrict__ w_att,
                const float* __restrict__ b_att,
                float* __restrict__ out,
                int n_groups)
{
    __shared__ float  s_words[NW * D];        // rows float4-aligned; stride 100 ≡ 4 mod 32
    __shared__ float4 s_type4[D4];
    __shared__ float4 s_wa4[NUM_HEADS * D4];  // flat == w_att layout
    __shared__ float4 s_ba4[NUM_HEADS * D4];
    __shared__ float4 s_e4[NW];               // exp(scores): {h0,h1,h2,h3} per word
    __shared__ float  s_inv[NUM_HEADS];
    __shared__ int    s_nz;

    const int t = threadIdx.x;
    const int g = blockIdx.x;
    if (g >= n_groups) return;

    // ---- phase 0: init + params ----
    if (t == 0) s_nz = 0;
    {
        float* wa = (float*)s_wa4;
        float* ba = (float*)s_ba4;
        for (int i = t; i < NUM_HEADS * D; i += NT) {
            wa[i] = w_att[i];
            ba[i] = b_att[i];
        }
    }
    __syncthreads();   // orders s_nz init before atomicOr; params before phase 2

    // ---- phase 1: stage 40x100 tile (LDG.128 + STS.128) ----
    const float4* __restrict__ gx4 =
        reinterpret_cast<const float4*>(x + (size_t)g * TILE_FLOATS);
    bool flag = false;
    for (int i4 = t; i4 < TILE_VEC4; i4 += NT) {
        float4 v = gx4[i4];
        flag |= (v.x != 0.f) | (v.y != 0.f) | (v.z != 0.f) | (v.w != 0.f);
        int w = i4 / D4;           // word row (0 = type_emb)
        int j = i4 - w * D4;
        if (w == 0) s_type4[j] = v;
        else        *reinterpret_cast<float4*>(&s_words[(w - 1) * D + 4 * j]) = v;
    }
    unsigned any = __ballot_sync(0xffffffffu, flag);
    if ((t & 31) == 0 && any) atomicOr(&s_nz, 1);
    __syncthreads();

    // ---- phase 2: one thread per (h,n): 156 threads / 5 warps all computing ----
    if (t < NUM_HEADS * NW) {
        const int h = t / NW;
        const int n = t - h * NW;
        const float4* __restrict__ wr4 = reinterpret_cast<const float4*>(&s_words[n * D]);
        const float4* __restrict__ wa  = &s_wa4[h * D4];
        const float4* __restrict__ ba  = &s_ba4[h * D4];
        float acc = 0.f;
        #pragma unroll 1
        for (int j = 0; j < D4; ++j) {
            float4 w  = wr4[j];      // conflict-free (stride 4 banks per lane in 8-lane phase)
            float4 ty = s_type4[j];  // broadcast
            float4 A  = wa[j];       // broadcast within head span
            float4 B  = ba[j];
            acc = fmaf(ty.x, leaky(fmaf(w.x, A.x, B.x)), acc);
            acc = fmaf(ty.y, leaky(fmaf(w.y, A.y, B.y)), acc);
            acc = fmaf(ty.z, leaky(fmaf(w.z, A.z, B.z)), acc);
            acc = fmaf(ty.w, leaky(fmaf(w.w, A.w, B.w)), acc);
        }
        ((float*)s_e4)[n * 4 + h] = __expf(acc);
    }
    __syncthreads();

    // ---- phase 3: per-head denominators, warp h reduces head h (no atomics) ----
    if (t < 4 * 32) {
        const int h = t >> 5, lane = t & 31;
        const float* ef = (const float*)s_e4;
        float v = (lane < NW) ? ef[lane * 4 + h] : 0.f;
        if (lane < NW - 32) v += ef[(lane + 32) * 4 + h];
        #pragma unroll
        for (int off = 16; off; off >>= 1)
            v += __shfl_down_sync(0xffffffffu, v, off);
        if (lane == 0) s_inv[h] = __fdividef(1.f, v);
    }
    __syncthreads();

    // ---- phase 4: one thread per column d, all 4 heads ----
    if (t < D) {
        float a0 = 0.f, a1 = 0.f, a2 = 0.f, a3 = 0.f;
        #pragma unroll 13
        for (int n = 0; n < NW; ++n) {
            float  w = s_words[n * D + t];   // 1 conflict-free wf
            float4 e = s_e4[n];              // LDS.128 broadcast
            a0 = fmaf(e.x, w, a0);
            a1 = fmaf(e.y, w, a1);
            a2 = fmaf(e.z, w, a2);
            a3 = fmaf(e.w, w, a3);
        }
        float* __restrict__ go = out + (size_t)g * (NUM_HEADS * D);
        if (s_nz) {
            go[t]         = a0 * s_inv[0];
            go[D + t]     = a1 * s_inv[1];
            go[2 * D + t] = a2 * s_inv[2];
            go[3 * D + t] = a3 * s_inv[3];
        } else {
            go[t] = 0.f; go[D + t] = 0.f; go[2 * D + t] = 0.f; go[3 * D + t] = 0.f;
        }
    }
}

extern "C" void kernel_launch(void* const* d_in, const int* in_sizes, int n_in,
                              void* d_out, int out_size)
{
    const float* x     = (const float*)d_in[0];
    const float* w_att = (const float*)d_in[1];
    const float* b_att = (const float*)d_in[2];
    float* out = (float*)d_out;

    int n_groups = in_sizes[0] / TILE_FLOATS;   // B*T*E = 4800
    tse_kernel<<<n_groups, NT>>>(x, w_att, b_att, out, n_groups);
}